// round 1
// baseline (speedup 1.0000x reference)
#include <cuda_runtime.h>

// Staggered 4th-order coefficients
#define C1 1.125f
#define C2 (-1.0f/24.0f)

// ---------------- Kernel 1: update_E ----------------
// dHz_dx[i] = (C1*(Hz[x]-Hz[x-1]) + C2*(Hz[x+1]-Hz[x-2])) * rdx
// dHx_dz[i] = (C1*(Hx[y]-Hx[y-1]) + C2*(Hx[y+1]-Hx[y-2])) * rdy
// m_Hz_x' = bx*m_Hz_x + ax*dHz_dx ; m_Hx_z' = by*m_Hx_z + ay*dHx_dz
// Ey' = ca*Ey + cb*((dHz_dx/kx + m_Hz_x') - (dHx_dz/ky + m_Hx_z'))
__global__ void __launch_bounds__(256) upd_E(
    const float* __restrict__ ca, const float* __restrict__ cb,
    const float* __restrict__ Ey, const float* __restrict__ Hx,
    const float* __restrict__ Hz,
    const float* __restrict__ mHxz, const float* __restrict__ mHzx,
    const float* __restrict__ ky, const float* __restrict__ ay,
    const float* __restrict__ by,
    const float* __restrict__ kx, const float* __restrict__ ax,
    const float* __restrict__ bx,
    const float* __restrict__ prdy, const float* __restrict__ prdx,
    float* __restrict__ outEy, float* __restrict__ outmHxz,
    float* __restrict__ outmHzx,
    int NY, int NX)
{
    int x = blockIdx.x * blockDim.x + threadIdx.x;
    int y = blockIdx.y * blockDim.y + threadIdx.y;
    int b = blockIdx.z;
    if (x >= NX || y >= NY) return;

    const float rdx = *prdx;
    const float rdy = *prdy;

    size_t plane = (size_t)NY * NX;
    size_t base  = (size_t)b * plane + (size_t)y * NX + x;

    // x-direction neighbors of Hz (zero-padded)
    float hz_0  = Hz[base];
    float hz_m1 = (x >= 1)     ? Hz[base - 1] : 0.0f;
    float hz_m2 = (x >= 2)     ? Hz[base - 2] : 0.0f;
    float hz_p1 = (x + 1 < NX) ? Hz[base + 1] : 0.0f;
    float dHz_dx = (C1 * (hz_0 - hz_m1) + C2 * (hz_p1 - hz_m2)) * rdx;

    // y-direction neighbors of Hx (zero-padded)
    float hx_0  = Hx[base];
    float hx_m1 = (y >= 1)     ? Hx[base - (size_t)NX]     : 0.0f;
    float hx_m2 = (y >= 2)     ? Hx[base - 2 * (size_t)NX] : 0.0f;
    float hx_p1 = (y + 1 < NY) ? Hx[base + (size_t)NX]     : 0.0f;
    float dHx_dz = (C1 * (hx_0 - hx_m1) + C2 * (hx_p1 - hx_m2)) * rdy;

    float mhzx = bx[x] * mHzx[base] + ax[x] * dHz_dx;
    float mhxz = by[y] * mHxz[base] + ay[y] * dHx_dz;

    size_t cidx = (size_t)y * NX + x;
    float ey = ca[cidx] * Ey[base] +
               cb[cidx] * ((dHz_dx / kx[x] + mhzx) - (dHx_dz / ky[y] + mhxz));

    outEy[base]   = ey;
    outmHzx[base] = mhzx;
    outmHxz[base] = mhxz;
}

// ---------------- Kernel 2: update_H ----------------
// dEy_dz[i] = (C1*(Ey[y+1]-Ey[y]) + C2*(Ey[y+2]-Ey[y-1])) * rdy
// dEy_dx[i] = (C1*(Ey[x+1]-Ey[x]) + C2*(Ey[x+2]-Ey[x-1])) * rdx
// m_Ey_z' = by_h*m_Ey_z + ay_h*dEy_dz ; m_Ey_x' = bx_h*m_Ey_x + ax_h*dEy_dx
// Hx' = Hx - cq*(dEy_dz/ky_h + m_Ey_z') ; Hz' = Hz + cq*(dEy_dx/kx_h + m_Ey_x')
__global__ void __launch_bounds__(256) upd_H(
    const float* __restrict__ cq,
    const float* __restrict__ EyNew,   // updated Ey (from kernel 1 output)
    const float* __restrict__ Hx, const float* __restrict__ Hz,
    const float* __restrict__ mEyx, const float* __restrict__ mEyz,
    const float* __restrict__ kyh, const float* __restrict__ ayh,
    const float* __restrict__ byh,
    const float* __restrict__ kxh, const float* __restrict__ axh,
    const float* __restrict__ bxh,
    const float* __restrict__ prdy, const float* __restrict__ prdx,
    float* __restrict__ outHx, float* __restrict__ outHz,
    float* __restrict__ outmEyx, float* __restrict__ outmEyz,
    int NY, int NX)
{
    int x = blockIdx.x * blockDim.x + threadIdx.x;
    int y = blockIdx.y * blockDim.y + threadIdx.y;
    int b = blockIdx.z;
    if (x >= NX || y >= NY) return;

    const float rdx = *prdx;
    const float rdy = *prdy;

    size_t plane = (size_t)NY * NX;
    size_t base  = (size_t)b * plane + (size_t)y * NX + x;

    // x-direction neighbors of new Ey
    float ey_0  = EyNew[base];
    float ey_m1 = (x >= 1)     ? EyNew[base - 1] : 0.0f;
    float ey_p1 = (x + 1 < NX) ? EyNew[base + 1] : 0.0f;
    float ey_p2 = (x + 2 < NX) ? EyNew[base + 2] : 0.0f;
    float dEy_dx = (C1 * (ey_p1 - ey_0) + C2 * (ey_p2 - ey_m1)) * rdx;

    // y-direction neighbors of new Ey
    float ey_ym1 = (y >= 1)     ? EyNew[base - (size_t)NX]     : 0.0f;
    float ey_yp1 = (y + 1 < NY) ? EyNew[base + (size_t)NX]     : 0.0f;
    float ey_yp2 = (y + 2 < NY) ? EyNew[base + 2 * (size_t)NX] : 0.0f;
    float dEy_dz = (C1 * (ey_yp1 - ey_0) + C2 * (ey_yp2 - ey_ym1)) * rdy;

    float meyz = byh[y] * mEyz[base] + ayh[y] * dEy_dz;
    float meyx = bxh[x] * mEyx[base] + axh[x] * dEy_dx;

    size_t cidx = (size_t)y * NX + x;
    float cqv = cq[cidx];

    outHx[base]   = Hx[base] - cqv * (dEy_dz / kyh[y] + meyz);
    outHz[base]   = Hz[base] + cqv * (dEy_dx / kxh[x] + meyx);
    outmEyz[base] = meyz;
    outmEyx[base] = meyx;
}

extern "C" void kernel_launch(void* const* d_in, const int* in_sizes, int n_in,
                              void* d_out, int out_size)
{
    // metadata order:
    // 0 ca, 1 cb, 2 cq, 3 Ey, 4 Hx, 5 Hz, 6 m_Hx_z, 7 m_Hz_x, 8 m_Ey_x,
    // 9 m_Ey_z, 10 ky, 11 ky_h, 12 ay, 13 ay_h, 14 by, 15 by_h,
    // 16 kx, 17 kx_h, 18 ax, 19 ax_h, 20 bx, 21 bx_h, 22 rdy, 23 rdx, 24 stencil
    const float* ca    = (const float*)d_in[0];
    const float* cb    = (const float*)d_in[1];
    const float* cq    = (const float*)d_in[2];
    const float* Ey    = (const float*)d_in[3];
    const float* Hx    = (const float*)d_in[4];
    const float* Hz    = (const float*)d_in[5];
    const float* mHxz  = (const float*)d_in[6];
    const float* mHzx  = (const float*)d_in[7];
    const float* mEyx  = (const float*)d_in[8];
    const float* mEyz  = (const float*)d_in[9];
    const float* ky    = (const float*)d_in[10];
    const float* kyh   = (const float*)d_in[11];
    const float* ay    = (const float*)d_in[12];
    const float* ayh   = (const float*)d_in[13];
    const float* by    = (const float*)d_in[14];
    const float* byh   = (const float*)d_in[15];
    const float* kx    = (const float*)d_in[16];
    const float* kxh   = (const float*)d_in[17];
    const float* ax    = (const float*)d_in[18];
    const float* axh   = (const float*)d_in[19];
    const float* bx    = (const float*)d_in[20];
    const float* bxh   = (const float*)d_in[21];
    const float* prdy  = (const float*)d_in[22];
    const float* prdx  = (const float*)d_in[23];
    // d_in[24] = stencil (fixed at 4; hardcoded coefficients)

    int NY = in_sizes[10];          // ky has NY elements
    int NX = in_sizes[16];          // kx has NX elements
    int B  = in_sizes[3] / (NY * NX);

    size_t plane = (size_t)NY * NX;
    size_t field = (size_t)B * plane;

    float* out = (float*)d_out;
    // output stack: [Ey, Hx, Hz, m_Hx_z, m_Hz_x, m_Ey_x, m_Ey_z]
    float* oEy   = out + 0 * field;
    float* oHx   = out + 1 * field;
    float* oHz   = out + 2 * field;
    float* omHxz = out + 3 * field;
    float* omHzx = out + 4 * field;
    float* omEyx = out + 5 * field;
    float* omEyz = out + 6 * field;

    dim3 block(128, 2, 1);
    dim3 grid((NX + 127) / 128, (NY + 1) / 2, B);

    upd_E<<<grid, block>>>(ca, cb, Ey, Hx, Hz, mHxz, mHzx,
                           ky, ay, by, kx, ax, bx, prdy, prdx,
                           oEy, omHxz, omHzx, NY, NX);

    upd_H<<<grid, block>>>(cq, oEy, Hx, Hz, mEyx, mEyz,
                           kyh, ayh, byh, kxh, axh, bxh, prdy, prdx,
                           oHx, oHz, omEyx, omEyz, NY, NX);
}

// round 2
// speedup vs baseline: 1.2419x; 1.2419x over previous
#include <cuda_runtime.h>

#define C1 1.125f
#define C2 (-1.0f/24.0f)

__device__ __forceinline__ float4 ld4(const float* p) {
    return *reinterpret_cast<const float4*>(p);
}
__device__ __forceinline__ void st4(float* p, float4 v) {
    *reinterpret_cast<float4*>(p) = v;
}
__device__ __forceinline__ float4 f4zero() { return make_float4(0.f,0.f,0.f,0.f); }

// ---------------- Kernel 1: update_E (vectorized x4) ----------------
__global__ void __launch_bounds__(256) upd_E(
    const float* __restrict__ ca, const float* __restrict__ cb,
    const float* __restrict__ Ey, const float* __restrict__ Hx,
    const float* __restrict__ Hz,
    const float* __restrict__ mHxz, const float* __restrict__ mHzx,
    const float* __restrict__ ky, const float* __restrict__ ay,
    const float* __restrict__ by,
    const float* __restrict__ kx, const float* __restrict__ ax,
    const float* __restrict__ bx,
    const float* __restrict__ prdy, const float* __restrict__ prdx,
    float* __restrict__ outEy, float* __restrict__ outmHxz,
    float* __restrict__ outmHzx,
    int NY, int NX)
{
    int x4 = (blockIdx.x * blockDim.x + threadIdx.x) * 4;
    int y  = blockIdx.y * blockDim.y + threadIdx.y;
    int b  = blockIdx.z;
    if (x4 >= NX || y >= NY) return;

    const float rdx = *prdx;
    const float rdy = *prdy;

    size_t plane = (size_t)NY * NX;
    size_t base  = (size_t)b * plane + (size_t)y * NX + x4;

    // ---- x-derivative of Hz: needs x-2..x+1 per lane ----
    float4 c = ld4(Hz + base);
    float4 p = (x4 >= 4)      ? ld4(Hz + base - 4) : f4zero();
    float4 n = (x4 + 4 < NX)  ? ld4(Hz + base + 4) : f4zero();

    float4 dHzdx;
    dHzdx.x = (C1 * (c.x - p.w) + C2 * (c.y - p.z)) * rdx;
    dHzdx.y = (C1 * (c.y - c.x) + C2 * (c.z - p.w)) * rdx;
    dHzdx.z = (C1 * (c.z - c.y) + C2 * (c.w - c.x)) * rdx;
    dHzdx.w = (C1 * (c.w - c.z) + C2 * (n.x - c.y)) * rdx;

    // ---- y-derivative of Hx: rows y-2, y-1, y, y+1 ----
    float4 r0  = ld4(Hx + base);
    float4 rm1 = (y >= 1)     ? ld4(Hx + base - (size_t)NX)     : f4zero();
    float4 rm2 = (y >= 2)     ? ld4(Hx + base - 2*(size_t)NX)   : f4zero();
    float4 rp1 = (y + 1 < NY) ? ld4(Hx + base + (size_t)NX)     : f4zero();

    float4 dHxdz;
    dHxdz.x = (C1 * (r0.x - rm1.x) + C2 * (rp1.x - rm2.x)) * rdy;
    dHxdz.y = (C1 * (r0.y - rm1.y) + C2 * (rp1.y - rm2.y)) * rdy;
    dHxdz.z = (C1 * (r0.z - rm1.z) + C2 * (rp1.z - rm2.z)) * rdy;
    dHxdz.w = (C1 * (r0.w - rm1.w) + C2 * (rp1.w - rm2.w)) * rdy;

    // ---- per-x coefficients ----
    float4 bx4 = ld4(bx + x4);
    float4 ax4 = ld4(ax + x4);
    float4 kx4 = ld4(kx + x4);
    float  byv = by[y], ayv = ay[y], kyv = ky[y];
    float  rky = 1.0f / kyv;

    float4 mzx = ld4(mHzx + base);
    mzx.x = bx4.x * mzx.x + ax4.x * dHzdx.x;
    mzx.y = bx4.y * mzx.y + ax4.y * dHzdx.y;
    mzx.z = bx4.z * mzx.z + ax4.z * dHzdx.z;
    mzx.w = bx4.w * mzx.w + ax4.w * dHzdx.w;

    float4 mxz = ld4(mHxz + base);
    mxz.x = byv * mxz.x + ayv * dHxdz.x;
    mxz.y = byv * mxz.y + ayv * dHxdz.y;
    mxz.z = byv * mxz.z + ayv * dHxdz.z;
    mxz.w = byv * mxz.w + ayv * dHxdz.w;

    size_t cidx = (size_t)y * NX + x4;
    float4 ca4 = ld4(ca + cidx);
    float4 cb4 = ld4(cb + cidx);
    float4 ey  = ld4(Ey + base);

    ey.x = ca4.x * ey.x + cb4.x * ((dHzdx.x / kx4.x + mzx.x) - (dHxdz.x * rky + mxz.x));
    ey.y = ca4.y * ey.y + cb4.y * ((dHzdx.y / kx4.y + mzx.y) - (dHxdz.y * rky + mxz.y));
    ey.z = ca4.z * ey.z + cb4.z * ((dHzdx.z / kx4.z + mzx.z) - (dHxdz.z * rky + mxz.z));
    ey.w = ca4.w * ey.w + cb4.w * ((dHzdx.w / kx4.w + mzx.w) - (dHxdz.w * rky + mxz.w));

    st4(outEy   + base, ey);
    st4(outmHzx + base, mzx);
    st4(outmHxz + base, mxz);
}

// ---------------- Kernel 2: update_H (vectorized x4) ----------------
__global__ void __launch_bounds__(256) upd_H(
    const float* __restrict__ cq,
    const float* __restrict__ EyNew,
    const float* __restrict__ Hx, const float* __restrict__ Hz,
    const float* __restrict__ mEyx, const float* __restrict__ mEyz,
    const float* __restrict__ kyh, const float* __restrict__ ayh,
    const float* __restrict__ byh,
    const float* __restrict__ kxh, const float* __restrict__ axh,
    const float* __restrict__ bxh,
    const float* __restrict__ prdy, const float* __restrict__ prdx,
    float* __restrict__ outHx, float* __restrict__ outHz,
    float* __restrict__ outmEyx, float* __restrict__ outmEyz,
    int NY, int NX)
{
    int x4 = (blockIdx.x * blockDim.x + threadIdx.x) * 4;
    int y  = blockIdx.y * blockDim.y + threadIdx.y;
    int b  = blockIdx.z;
    if (x4 >= NX || y >= NY) return;

    const float rdx = *prdx;
    const float rdy = *prdy;

    size_t plane = (size_t)NY * NX;
    size_t base  = (size_t)b * plane + (size_t)y * NX + x4;

    // ---- x-derivative of new Ey: needs x-1..x+2 per lane ----
    float4 c = ld4(EyNew + base);
    float4 p = (x4 >= 4)     ? ld4(EyNew + base - 4) : f4zero();
    float4 n = (x4 + 4 < NX) ? ld4(EyNew + base + 4) : f4zero();

    float4 dEydx;
    dEydx.x = (C1 * (c.y - c.x) + C2 * (c.z - p.w)) * rdx;
    dEydx.y = (C1 * (c.z - c.y) + C2 * (c.w - c.x)) * rdx;
    dEydx.z = (C1 * (c.w - c.z) + C2 * (n.x - c.y)) * rdx;
    dEydx.w = (C1 * (n.x - c.w) + C2 * (n.y - c.z)) * rdx;

    // ---- y-derivative of new Ey: rows y-1, y, y+1, y+2 ----
    float4 rm1 = (y >= 1)     ? ld4(EyNew + base - (size_t)NX)   : f4zero();
    float4 rp1 = (y + 1 < NY) ? ld4(EyNew + base + (size_t)NX)   : f4zero();
    float4 rp2 = (y + 2 < NY) ? ld4(EyNew + base + 2*(size_t)NX) : f4zero();

    float4 dEydz;
    dEydz.x = (C1 * (rp1.x - c.x) + C2 * (rp2.x - rm1.x)) * rdy;
    dEydz.y = (C1 * (rp1.y - c.y) + C2 * (rp2.y - rm1.y)) * rdy;
    dEydz.z = (C1 * (rp1.z - c.z) + C2 * (rp2.z - rm1.z)) * rdy;
    dEydz.w = (C1 * (rp1.w - c.w) + C2 * (rp2.w - rm1.w)) * rdy;

    float4 bxh4 = ld4(bxh + x4);
    float4 axh4 = ld4(axh + x4);
    float4 kxh4 = ld4(kxh + x4);
    float  byhv = byh[y], ayhv = ayh[y], kyhv = kyh[y];
    float  rkyh = 1.0f / kyhv;

    float4 mez = ld4(mEyz + base);
    mez.x = byhv * mez.x + ayhv * dEydz.x;
    mez.y = byhv * mez.y + ayhv * dEydz.y;
    mez.z = byhv * mez.z + ayhv * dEydz.z;
    mez.w = byhv * mez.w + ayhv * dEydz.w;

    float4 mex = ld4(mEyx + base);
    mex.x = bxh4.x * mex.x + axh4.x * dEydx.x;
    mex.y = bxh4.y * mex.y + axh4.y * dEydx.y;
    mex.z = bxh4.z * mex.z + axh4.z * dEydx.z;
    mex.w = bxh4.w * mex.w + axh4.w * dEydx.w;

    size_t cidx = (size_t)y * NX + x4;
    float4 cq4 = ld4(cq + cidx);

    float4 hx = ld4(Hx + base);
    hx.x = hx.x - cq4.x * (dEydz.x * rkyh + mez.x);
    hx.y = hx.y - cq4.y * (dEydz.y * rkyh + mez.y);
    hx.z = hx.z - cq4.z * (dEydz.z * rkyh + mez.z);
    hx.w = hx.w - cq4.w * (dEydz.w * rkyh + mez.w);

    float4 hz = ld4(Hz + base);
    hz.x = hz.x + cq4.x * (dEydx.x / kxh4.x + mex.x);
    hz.y = hz.y + cq4.y * (dEydx.y / kxh4.y + mex.y);
    hz.z = hz.z + cq4.z * (dEydx.z / kxh4.z + mex.z);
    hz.w = hz.w + cq4.w * (dEydx.w / kxh4.w + mex.w);

    st4(outHx   + base, hx);
    st4(outHz   + base, hz);
    st4(outmEyz + base, mez);
    st4(outmEyx + base, mex);
}

extern "C" void kernel_launch(void* const* d_in, const int* in_sizes, int n_in,
                              void* d_out, int out_size)
{
    const float* ca    = (const float*)d_in[0];
    const float* cb    = (const float*)d_in[1];
    const float* cq    = (const float*)d_in[2];
    const float* Ey    = (const float*)d_in[3];
    const float* Hx    = (const float*)d_in[4];
    const float* Hz    = (const float*)d_in[5];
    const float* mHxz  = (const float*)d_in[6];
    const float* mHzx  = (const float*)d_in[7];
    const float* mEyx  = (const float*)d_in[8];
    const float* mEyz  = (const float*)d_in[9];
    const float* ky    = (const float*)d_in[10];
    const float* kyh   = (const float*)d_in[11];
    const float* ay    = (const float*)d_in[12];
    const float* ayh   = (const float*)d_in[13];
    const float* by    = (const float*)d_in[14];
    const float* byh   = (const float*)d_in[15];
    const float* kx    = (const float*)d_in[16];
    const float* kxh   = (const float*)d_in[17];
    const float* ax    = (const float*)d_in[18];
    const float* axh   = (const float*)d_in[19];
    const float* bx    = (const float*)d_in[20];
    const float* bxh   = (const float*)d_in[21];
    const float* prdy  = (const float*)d_in[22];
    const float* prdx  = (const float*)d_in[23];

    int NY = in_sizes[10];
    int NX = in_sizes[16];
    int B  = in_sizes[3] / (NY * NX);

    size_t plane = (size_t)NY * NX;
    size_t field = (size_t)B * plane;

    float* out = (float*)d_out;
    float* oEy   = out + 0 * field;
    float* oHx   = out + 1 * field;
    float* oHz   = out + 2 * field;
    float* omHxz = out + 3 * field;
    float* omHzx = out + 4 * field;
    float* omEyx = out + 5 * field;
    float* omEyz = out + 6 * field;

    // each thread: 4 x-elements
    dim3 block(64, 4, 1);
    int nx4 = NX / 4;                       // NX=2048 -> 512
    dim3 grid((nx4 + 63) / 64, (NY + 3) / 4, B);

    upd_E<<<grid, block>>>(ca, cb, Ey, Hx, Hz, mHxz, mHzx,
                           ky, ay, by, kx, ax, bx, prdy, prdx,
                           oEy, omHxz, omHzx, NY, NX);

    upd_H<<<grid, block>>>(cq, oEy, Hx, Hz, mEyx, mEyz,
                           kyh, ayh, byh, kxh, axh, bxh, prdy, prdx,
                           oHx, oHz, omEyx, omEyz, NY, NX);
}